// round 6
// baseline (speedup 1.0000x reference)
#include <cuda_runtime.h>
#include <math.h>

#define NE    16
#define NU    8
#define NA    4
#define NSV   256
#define NPV   32
#define PSTR  33
#define NFB   4
#define NDET  16
#define NORB  128
#define NTH   512
#define SBLK  (NE * NSV)       // 4096 per-walker s buffer
#define PBLK  (NE * NE * PSTR) // 8448 per-walker pair buffer
#define PUB   (NE * NPV)       // 512 per-walker pu/pd
#define M2BLK (2 * NSV)        // 512 per-walker [mu;md]

typedef unsigned long long u64;

#define FFMA2(d, a, b) asm volatile("fma.rn.f32x2 %0, %1, %2, %0;" : "+l"(d) : "l"(a), "l"(b))
#define BARX() asm volatile("bar.sync 2, 256;" ::: "memory")
#define BARY() asm volatile("bar.sync 1, 256;" ::: "memory")

__device__ __forceinline__ u64 pk2(float x, float y) {
    u64 d;
    asm("mov.b64 %0, {%1, %2};" : "=l"(d) : "r"(__float_as_uint(x)), "r"(__float_as_uint(y)));
    return d;
}
__device__ __forceinline__ float2 upk2(u64 d) {
    unsigned int lo, hi;
    asm("mov.b64 {%0, %1}, %2;" : "=r"(lo), "=r"(hi) : "l"(d));
    return make_float2(__uint_as_float(lo), __uint_as_float(hi));
}
__device__ __forceinline__ int imin(int a, int b) { return a < b ? a : b; }
__device__ __forceinline__ int imax(int a, int b) { return a > b ? a : b; }

struct SM {
    float s_a[2 * SBLK];      // 8192
    float s_b[2 * SBLK];      // 8192
    float p[2 * PBLK];        // 16896 ; post-stream alias per walker: sw[2048]|opart[6144]|ldv/sgv
    float m2[2 * M2BLK];      // 1024  [w][mu(KS);md(KS)]
    float pu[2][2 * PUB];     // 2048  [buf][w]
    float pd[2][2 * PUB];     // 2048
    float scratch[16 * NSV];  // 4096  fb_base partials [g*2+w][c]
    float part[2 * SBLK];     // 8192  fb2 kg1 partials [w][r][c]
    float pw[NPV * NPV];      // 1024
    float pbv[NPV];
    float r_s[2 * NE * 3];    // 96
    float a_s[NA * 3];
    float env[2 * NE];
};

// 16 rows x 4 cols (2 col-pairs, FFMA2) over a k-segment.
__device__ __forceinline__ void acc_seg16(u64* acc, const float* __restrict__ Wp,
                                          const float* act, int astride, int n4) {
#pragma unroll 1
    for (int t = 0; t < n4; ++t) {
        u64 wl[4], wh[4];
#pragma unroll
        for (int k = 0; k < 4; ++k) {
            float4 wv = __ldg((const float4*)(Wp + k * NSV));
            wl[k] = pk2(wv.x, wv.y);
            wh[k] = pk2(wv.z, wv.w);
        }
#pragma unroll
        for (int r = 0; r < 16; ++r) {
            float4 v = *(const float4*)(act + r * astride);
            u64 d;
            d = pk2(v.x, v.x); FFMA2(acc[2 * r], d, wl[0]); FFMA2(acc[2 * r + 1], d, wh[0]);
            d = pk2(v.y, v.y); FFMA2(acc[2 * r], d, wl[1]); FFMA2(acc[2 * r + 1], d, wh[1]);
            d = pk2(v.z, v.z); FFMA2(acc[2 * r], d, wl[2]); FFMA2(acc[2 * r + 1], d, wh[2]);
            d = pk2(v.w, v.w); FFMA2(acc[2 * r], d, wl[3]); FFMA2(acc[2 * r + 1], d, wh[3]);
        }
        Wp += 4 * NSV;
        act += 4;
    }
}

// base[w][c] = bias[c] + [mu;md]_w @ W rows [KS,3KS). 8 k-groups x 64 cols, both walkers
// per weight load (FFMA2 col-pairs). All 512 threads.
template <int KS>
__device__ __forceinline__ void fb_base(SM* sm, const float* __restrict__ W,
                                        const float* __restrict__ bias, int tid) {
    const int g = tid >> 6, c0 = (tid & 63) << 2;
    const int CH = (2 * KS) / 8;
    const int k0 = g * CH;
    u64 a00, a01, a10, a11;
    if (g == 0) {
        float4 b4 = __ldg((const float4*)(bias + c0));
        a00 = pk2(b4.x, b4.y); a01 = pk2(b4.z, b4.w);
        a10 = a00; a11 = a01;
    } else {
        a00 = a01 = a10 = a11 = 0ull;
    }
    const float* Wp = W + (KS + k0) * NSV + c0;
    const float* m0 = sm->m2 + k0;
    const float* m1 = sm->m2 + M2BLK + k0;
#pragma unroll 1
    for (int t = 0; t < CH / 4; ++t) {
        float4 ma = *(const float4*)m0;
        float4 mb = *(const float4*)m1;
        float maa[4] = {ma.x, ma.y, ma.z, ma.w};
        float mbb[4] = {mb.x, mb.y, mb.z, mb.w};
#pragma unroll
        for (int k = 0; k < 4; ++k) {
            float4 wv = __ldg((const float4*)(Wp + k * NSV));
            u64 wlo = pk2(wv.x, wv.y), whi = pk2(wv.z, wv.w);
            u64 da = pk2(maa[k], maa[k]), db = pk2(mbb[k], mbb[k]);
            FFMA2(a00, da, wlo); FFMA2(a01, da, whi);
            FFMA2(a10, db, wlo); FFMA2(a11, db, whi);
        }
        Wp += 4 * NSV; m0 += 4; m1 += 4;
    }
    float2 x = upk2(a00), y = upk2(a01);
    *(float4*)(sm->scratch + (g * 2 + 0) * NSV + c0) = make_float4(x.x, x.y, y.x, y.y);
    x = upk2(a10); y = upk2(a11);
    *(float4*)(sm->scratch + (g * 2 + 1) * NSV + c0) = make_float4(x.x, x.y, y.x, y.y);
}

// fb2: X-half (tid<256). kg(2) x walker(2) x 64 col-threads, 16 rows x 4 cols each.
template <int KS, int KP, bool RES>
__device__ __forceinline__ void fb2(SM* sm, const float* __restrict__ W,
                                    const float* sin_, float* sout,
                                    const float* pub, const float* pdb, int tid) {
    const int kg = tid >> 7;
    const int w  = (tid >> 6) & 1;
    const int c0 = (tid & 63) << 2;
    const float* sw_ = sin_ + w * SBLK;
    float* so_ = sout + w * SBLK;
    const int K = KS + 2 * KP, H = K / 2;
    const int ka = kg * H, kb = ka + H;
    u64 acc[32];
#pragma unroll
    for (int i = 0; i < 32; ++i) acc[i] = 0ull;
    {   int a = ka, b2 = imin(kb, KS);
        if (b2 > a) acc_seg16(acc, W + a * NSV + c0, sw_ + a, NSV, (b2 - a) / 4); }
    {   int a = imax(ka, KS), b2 = imin(kb, KS + KP);
        if (b2 > a) acc_seg16(acc, W + (2 * KS + a) * NSV + c0, pub + w * PUB + (a - KS), NPV, (b2 - a) / 4); }
    {   int a = imax(ka, KS + KP), b2 = imin(kb, K);
        if (b2 > a) acc_seg16(acc, W + (2 * KS + a) * NSV + c0, pdb + w * PUB + (a - KS - KP), NPV, (b2 - a) / 4); }
    if (kg == 1) {
#pragma unroll
        for (int r = 0; r < 16; ++r) {
            float2 x = upk2(acc[2 * r]), y = upk2(acc[2 * r + 1]);
            *(float4*)(sm->part + w * SBLK + r * NSV + c0) = make_float4(x.x, x.y, y.x, y.y);
        }
    }
    BARX();
    if (kg == 0) {
        float4 bb = make_float4(0.f, 0.f, 0.f, 0.f);
#pragma unroll
        for (int g = 0; g < 8; ++g) {
            float4 s4 = *(const float4*)(sm->scratch + (g * 2 + w) * NSV + c0);
            bb.x += s4.x; bb.y += s4.y; bb.z += s4.z; bb.w += s4.w;
        }
#pragma unroll
        for (int r = 0; r < 16; ++r) {
            float2 x = upk2(acc[2 * r]), y = upk2(acc[2 * r + 1]);
            float4 pp = *(const float4*)(sm->part + w * SBLK + r * NSV + c0);
            float4 o;
            o.x = tanhf(x.x + pp.x + bb.x);
            o.y = tanhf(x.y + pp.y + bb.y);
            o.z = tanhf(y.x + pp.z + bb.z);
            o.w = tanhf(y.y + pp.w + bb.w);
            if (RES) {
                float4 rr = *(const float4*)(sw_ + r * NSV + c0);
                o.x += rr.x; o.y += rr.y; o.z += rr.z; o.w += rr.w;
            }
            *(float4*)(so_ + r * NSV + c0) = o;
        }
    }
}

// p-stream matmul: Y-half (ty in [0,256)). 2 rows/thread (one per walker), fused weight reuse.
template <int KIN, bool RES>
__device__ __forceinline__ void pY(SM* sm, const float* __restrict__ W,
                                   const float* __restrict__ bias, int ty) {
    for (int i = ty; i < KIN * NPV; i += 256) sm->pw[i] = __ldg(W + i);
    if (ty < NPV) sm->pbv[ty] = __ldg(bias + ty);
    BARY();
    float* pr0 = sm->p + ty * PSTR;
    float* pr1 = sm->p + PBLK + ty * PSTR;
    float i0[KIN], i1[KIN];
#pragma unroll
    for (int k = 0; k < KIN; ++k) { i0[k] = pr0[k]; i1[k] = pr1[k]; }
#pragma unroll
    for (int cb = 0; cb < NPV; cb += 4) {
        float4 b4 = *(const float4*)(sm->pbv + cb);
        float4 a0 = b4, a1 = b4;
#pragma unroll
        for (int k = 0; k < KIN; ++k) {
            float4 wv = *(const float4*)(sm->pw + k * NPV + cb);
            a0.x = fmaf(i0[k], wv.x, a0.x); a0.y = fmaf(i0[k], wv.y, a0.y);
            a0.z = fmaf(i0[k], wv.z, a0.z); a0.w = fmaf(i0[k], wv.w, a0.w);
            a1.x = fmaf(i1[k], wv.x, a1.x); a1.y = fmaf(i1[k], wv.y, a1.y);
            a1.z = fmaf(i1[k], wv.z, a1.z); a1.w = fmaf(i1[k], wv.w, a1.w);
        }
        pr0[cb + 0] = RES ? tanhf(a0.x) + i0[cb + 0] : tanhf(a0.x);
        pr0[cb + 1] = RES ? tanhf(a0.y) + i0[cb + 1] : tanhf(a0.y);
        pr0[cb + 2] = RES ? tanhf(a0.z) + i0[cb + 2] : tanhf(a0.z);
        pr0[cb + 3] = RES ? tanhf(a0.w) + i0[cb + 3] : tanhf(a0.w);
        pr1[cb + 0] = RES ? tanhf(a1.x) + i1[cb + 0] : tanhf(a1.x);
        pr1[cb + 1] = RES ? tanhf(a1.y) + i1[cb + 1] : tanhf(a1.y);
        pr1[cb + 2] = RES ? tanhf(a1.z) + i1[cb + 2] : tanhf(a1.z);
        pr1[cb + 3] = RES ? tanhf(a1.w) + i1[cb + 3] : tanhf(a1.w);
    }
    BARY();
}

__device__ __forceinline__ void means_p_core(SM* sm, int kp, float* dpu, float* dpd,
                                             int start, int stride) {
    for (int idx = start; idx < 2 * NE * NPV; idx += stride) {
        int w = idx >> 9, rem = idx & 511;
        int j = rem >> 5, f = rem & 31;
        if (f < kp) {
            const float* pb = sm->p + w * PBLK;
            float a = 0.f, b = 0.f;
#pragma unroll
            for (int i = 0; i < NU; ++i) a += pb[(i * NE + j) * PSTR + f];
#pragma unroll
            for (int i = NU; i < NE; ++i) b += pb[(i * NE + j) * PSTR + f];
            dpu[w * PUB + j * NPV + f] = a * 0.125f;
            dpd[w * PUB + j * NPV + f] = b * 0.125f;
        }
    }
}

template <int KS>
__device__ __forceinline__ void means_s(SM* sm, const float* s, int tid) {
    const int sh = (KS == 256) ? 8 : 4;
    if (tid < 2 * KS) {
        int w = tid >> sh, c = tid & (KS - 1);
        const float* sb = s + w * SBLK;
        float a = 0.f, b = 0.f;
#pragma unroll
        for (int e = 0; e < NU; ++e) a += sb[e * NSV + c];
#pragma unroll
        for (int e = NU; e < NE; ++e) b += sb[e * NSV + c];
        sm->m2[w * M2BLK + c] = a * 0.125f;
        sm->m2[w * M2BLK + KS + c] = b * 0.125f;
    }
}

// Orbitals: all 512 threads = walker(2) x spin(2) x kc(4) x 32 col-threads.
__device__ __forceinline__ void orbitals(SM* sm, const float* sfin,
                                         const float* __restrict__ wuW, const float* __restrict__ wub,
                                         const float* __restrict__ wdW, const float* __restrict__ wdb,
                                         int tid) {
    const int w = tid >> 8;
    const int t2 = tid & 255;
    const int g = t2 >> 5, c0 = (t2 & 31) << 2;
    const int spin = g >> 2, kc = g & 3;
    const float* W = spin ? wdW : wuW;
    const float* bias = spin ? wdb : wub;
    const int e0 = spin * 8;
    const float* sf = sfin + w * SBLK;
    float* pbase = sm->p + w * PBLK;
    float4 acc[8];
#pragma unroll
    for (int r = 0; r < 8; ++r) acc[r] = make_float4(0.f, 0.f, 0.f, 0.f);
    const float* Wp = W + (kc * 64) * NORB + c0;
    const float* ap = sf + e0 * NSV + kc * 64;
#pragma unroll 1
    for (int t = 0; t < 16; ++t) {
        float4 w0 = __ldg((const float4*)(Wp + 0 * NORB));
        float4 w1 = __ldg((const float4*)(Wp + 1 * NORB));
        float4 w2 = __ldg((const float4*)(Wp + 2 * NORB));
        float4 w3 = __ldg((const float4*)(Wp + 3 * NORB));
#pragma unroll
        for (int r = 0; r < 8; ++r) {
            float4 v = *(const float4*)(ap + r * NSV);
            acc[r].x = fmaf(v.x, w0.x, fmaf(v.y, w1.x, fmaf(v.z, w2.x, fmaf(v.w, w3.x, acc[r].x))));
            acc[r].y = fmaf(v.x, w0.y, fmaf(v.y, w1.y, fmaf(v.z, w2.y, fmaf(v.w, w3.y, acc[r].y))));
            acc[r].z = fmaf(v.x, w0.z, fmaf(v.y, w1.z, fmaf(v.z, w2.z, fmaf(v.w, w3.z, acc[r].z))));
            acc[r].w = fmaf(v.x, w0.w, fmaf(v.y, w1.w, fmaf(v.z, w2.w, fmaf(v.w, w3.w, acc[r].w))));
        }
        Wp += 4 * NORB;
        ap += 4;
    }
    float* opart = pbase + 2048;
    if (kc) {
#pragma unroll
        for (int r = 0; r < 8; ++r)
            *(float4*)(opart + (spin * 3 + kc - 1) * 1024 + r * NORB + c0) = acc[r];
    }
    __syncthreads();
    if (kc == 0) {
        float4 b4 = *(const float4*)(bias + c0);
#pragma unroll
        for (int r = 0; r < 8; ++r) {
            float4 s = acc[r];
            float4 p0 = *(const float4*)(opart + (spin * 3 + 0) * 1024 + r * NORB + c0);
            float4 p1 = *(const float4*)(opart + (spin * 3 + 1) * 1024 + r * NORB + c0);
            float4 p2 = *(const float4*)(opart + (spin * 3 + 2) * 1024 + r * NORB + c0);
            float ev = sm->env[w * NE + e0 + r];
            float4 o;
            o.x = (s.x + p0.x + p1.x + p2.x + b4.x) * ev;
            o.y = (s.y + p0.y + p1.y + p2.y + b4.y) * ev;
            o.z = (s.z + p0.z + p1.z + p2.z + b4.z) * ev;
            o.w = (s.w + p0.w + p1.w + p2.w + b4.w) * ev;
            *(float4*)(pbase + (e0 + r) * NORB + c0) = o;
        }
    }
    __syncthreads();
}

__global__ void __launch_bounds__(NTH, 1) ansatz_kernel(
    const float* __restrict__ r, const float* __restrict__ a,
    const float* __restrict__ sW0, const float* __restrict__ sb0,
    const float* __restrict__ sW, const float* __restrict__ sb,
    const float* __restrict__ pW0, const float* __restrict__ pb0,
    const float* __restrict__ pW, const float* __restrict__ pb,
    const float* __restrict__ vW, const float* __restrict__ vb,
    const float* __restrict__ wuW, const float* __restrict__ wub,
    const float* __restrict__ wdW, const float* __restrict__ wdb,
    const float* __restrict__ wfW, float* __restrict__ out) {
    extern __shared__ float smem_raw[];
    SM* sm = reinterpret_cast<SM*>(smem_raw);
    const int tid = threadIdx.x;
    const int blk = blockIdx.x;

    if (tid < 96) sm->r_s[tid] = r[blk * 96 + tid];
    if (tid >= 128 && tid < 128 + NA * 3) sm->a_s[tid - 128] = a[tid - 128];
    __syncthreads();

    // ---- embedding ----
    if (tid < 32) {
        int w = tid >> 4, e = tid & 15;
        const float* rs = sm->r_s + w * 48;
        float rx = rs[e * 3], ry = rs[e * 3 + 1], rz = rs[e * 3 + 2];
        float envv = 0.f;
        float* srow = sm->s_a + w * SBLK + e * NSV;
#pragma unroll
        for (int at = 0; at < NA; ++at) {
            float dx = rx - sm->a_s[at * 3];
            float dy = ry - sm->a_s[at * 3 + 1];
            float dz = rz - sm->a_s[at * 3 + 2];
            float l = sqrtf(dx * dx + dy * dy + dz * dz);
            srow[at * 4 + 0] = dx; srow[at * 4 + 1] = dy;
            srow[at * 4 + 2] = dz; srow[at * 4 + 3] = l;
            envv += expf(-l);
        }
        sm->env[w * NE + e] = envv;
    }
    {
        int w = tid >> 8, pr = tid & 255;
        int i = pr >> 4, j = pr & 15;
        const float* rs = sm->r_s + w * 48;
        float dx = rs[j * 3 + 0] - rs[i * 3 + 0];
        float dy = rs[j * 3 + 1] - rs[i * 3 + 1];
        float dz = rs[j * 3 + 2] - rs[i * 3 + 2];
        float l = (i == j) ? sqrtf(3.0f) : sqrtf(dx * dx + dy * dy + dz * dz);
        float* prow = sm->p + w * PBLK + pr * PSTR;
        prow[0] = dx; prow[1] = dy; prow[2] = dz; prow[3] = l;
    }
    __syncthreads();

    means_s<16>(sm, sm->s_a, tid);
    means_p_core(sm, 4, sm->pu[0], sm->pd[0], tid, NTH);
    __syncthreads();

    // ---- layer 0 ----
    fb_base<16>(sm, sW0, sb0, tid);
    __syncthreads();
    if (tid < 256) {
        fb2<16, 4, false>(sm, sW0, sm->s_a, sm->s_b, sm->pu[0], sm->pd[0], tid);
    } else {
        int ty = tid - 256;
        pY<4, false>(sm, pW0, pb0, ty);
        means_p_core(sm, 32, sm->pu[1], sm->pd[1], ty, 256);
    }
    __syncthreads();

    // ---- residual layers ----
    float* cur = sm->s_b;
    float* oth = sm->s_a;
    int pbuf = 1;
    for (int l = 0; l < NFB; ++l) {
        means_s<256>(sm, cur, tid);
        __syncthreads();
        const float* Wl = sW + l * (832 * NSV);
        fb_base<256>(sm, Wl, sb + l * NSV, tid);
        __syncthreads();
        if (tid < 256) {
            fb2<256, 32, true>(sm, Wl, cur, oth, sm->pu[pbuf], sm->pd[pbuf], tid);
        } else {
            int ty = tid - 256;
            pY<32, true>(sm, pW + l * (NPV * NPV), pb + l * NPV, ty);
            means_p_core(sm, 32, sm->pu[pbuf ^ 1], sm->pd[pbuf ^ 1], ty, 256);
        }
        __syncthreads();
        float* t = cur; cur = oth; oth = t;
        pbuf ^= 1;
    }

    // ---- final projection ----
    means_s<256>(sm, cur, tid);
    __syncthreads();
    fb_base<256>(sm, vW, vb, tid);
    __syncthreads();
    if (tid < 256)
        fb2<256, 32, false>(sm, vW, cur, oth, sm->pu[pbuf], sm->pd[pbuf], tid);
    __syncthreads();

    // ---- orbitals (writes sw into p-region alias, env applied) ----
    orbitals(sm, oth, wuW, wub, wdW, wdb, tid);

    // ---- 8x8 slogdets: 64 threads = 2 walkers x 2 spins x 16 dets ----
    if (tid < 64) {
        int w = tid >> 5, spin = (tid >> 4) & 1, d = tid & 15;
        float* pbase = sm->p + w * PBLK;
        const float* swp = pbase + spin * NU * NORB;
        float M[8][8];
#pragma unroll
        for (int o = 0; o < 8; ++o)
#pragma unroll
            for (int e = 0; e < 8; ++e)
                M[o][e] = swp[e * NORB + o * NDET + d];
        float ld = 0.f, sg = 1.f;
        for (int k = 0; k < 8; ++k) {
            int piv = k;
            float mx = fabsf(M[k][k]);
            for (int i2 = k + 1; i2 < 8; ++i2) {
                float v = fabsf(M[i2][k]);
                if (v > mx) { mx = v; piv = i2; }
            }
            if (piv != k) {
                for (int j2 = 0; j2 < 8; ++j2) {
                    float t = M[k][j2]; M[k][j2] = M[piv][j2]; M[piv][j2] = t;
                }
                sg = -sg;
            }
            float pvv = M[k][k];
            ld += logf(fabsf(pvv));
            if (pvv < 0.f) sg = -sg;
            float inv = 1.0f / pvv;
            for (int i2 = k + 1; i2 < 8; ++i2) {
                float f = M[i2][k] * inv;
                for (int j2 = k + 1; j2 < 8; ++j2)
                    M[i2][j2] = fmaf(-f, M[k][j2], M[i2][j2]);
            }
        }
        float* ldv = pbase + 8192;
        float* sgv = pbase + 8224;
        ldv[spin * NDET + d] = ld;
        sgv[spin * NDET + d] = sg;
    }
    __syncthreads();

    // ---- combine ----
    if (tid < 2) {
        int w = tid;
        const float* ldv = sm->p + w * PBLK + 8192;
        const float* sgv = sm->p + w * PBLK + 8224;
        float m = -3.402823e38f;
        float ldt[NDET], sgt[NDET];
#pragma unroll
        for (int d = 0; d < NDET; ++d) {
            ldt[d] = ldv[d] + ldv[NDET + d];
            sgt[d] = sgv[d] * sgv[NDET + d];
            m = fmaxf(m, ldt[d]);
        }
        float s = 0.f;
#pragma unroll
        for (int d = 0; d < NDET; ++d)
            s += sgt[d] * expf(ldt[d] - m) * __ldg(wfW + d);
        out[blk * 2 + w] = logf(fabsf(s)) + m;
    }
}

extern "C" void kernel_launch(void* const* d_in, const int* in_sizes, int n_in,
                              void* d_out, int out_size) {
    const float* r   = (const float*)d_in[0];
    const float* a   = (const float*)d_in[1];
    const float* sW0 = (const float*)d_in[2];
    const float* sb0 = (const float*)d_in[3];
    const float* sW  = (const float*)d_in[4];
    const float* sb  = (const float*)d_in[5];
    const float* pW0 = (const float*)d_in[6];
    const float* pb0 = (const float*)d_in[7];
    const float* pW  = (const float*)d_in[8];
    const float* pb  = (const float*)d_in[9];
    const float* vW  = (const float*)d_in[10];
    const float* vb  = (const float*)d_in[11];
    const float* wuW = (const float*)d_in[12];
    const float* wub = (const float*)d_in[13];
    const float* wdW = (const float*)d_in[14];
    const float* wdb = (const float*)d_in[15];
    const float* wfW = (const float*)d_in[16];
    float* out = (float*)d_out;

    int B = in_sizes[0] / (NE * 3);
    size_t smem = sizeof(SM);
    cudaFuncSetAttribute(ansatz_kernel, cudaFuncAttributeMaxDynamicSharedMemorySize,
                         (int)smem);
    ansatz_kernel<<<B / 2, NTH, smem>>>(r, a, sW0, sb0, sW, sb, pW0, pb0, pW, pb,
                                        vW, vb, wuW, wub, wdW, wdb, wfW, out);
}